// round 7
// baseline (speedup 1.0000x reference)
#include <cuda_runtime.h>
#include <cstdint>

// Fixed problem shapes
#define NIMG      262144     // 4096 * 64 images
#define IMG_ELEMS 128        // 16 x 8
#define IMG_W     8
#define OUT_ELEMS 84         // 14 x 6
#define OUT_W     6

#define THREADS   224                      // 7 warps: warp = row-group, lane = image
#define IMGS      32                       // images per tile
#define NTILES    (NIMG / IMGS)            // 8192

// Input smem: 33 float4 (132 floats) per image -> conflict-free LDS.128
#define PAD_F4   33
#define PAD_F    132

#define NSM           148
#define BLOCKS_PER_SM 5
#define GRID          (NSM * BLOCKS_PER_SM)   // 740 persistent blocks

#define F4_PER_TILE (IMGS * IMG_ELEMS / 4)    // 1024

__device__ __forceinline__ void cpasync16(uint32_t saddr, const void* g) {
    asm volatile("cp.async.cg.shared.global [%0], [%1], 16;\n"
                 :: "r"(saddr), "l"(g));
}
__device__ __forceinline__ void cp_commit() {
    asm volatile("cp.async.commit_group;\n");
}
__device__ __forceinline__ void cp_wait1() {
    asm volatile("cp.async.wait_group 1;\n");
}

__device__ __forceinline__ void loadrow(float* d, const float* p) {
    float4 lo = *(const float4*)p;
    float4 hi = *(const float4*)(p + 4);
    d[0] = lo.x; d[1] = lo.y; d[2] = lo.z; d[3] = lo.w;
    d[4] = hi.x; d[5] = hi.y; d[6] = hi.z; d[7] = hi.w;
}

__global__ __launch_bounds__(THREADS, BLOCKS_PER_SM)
void conv3x3_relu_kernel(const float* __restrict__ x,
                         const float* __restrict__ kern,
                         float* __restrict__ out)
{
    __shared__ float si[2][IMGS * PAD_F];   // 2 x 16896 B = 33792 B total

    const int tid = threadIdx.x;

    // Thread role: image = lane, 2-output-row group = warp (0..6)
    const int g   = tid >> 5;             // warp-uniform row group
    const int img = tid & 31;             // lane -> conflict-free LDS (stride 132)

    const float k0 = kern[0], k1 = kern[1], k2 = kern[2];
    const float k3 = kern[3], k4 = kern[4], k5 = kern[5];
    const float k6 = kern[6], k7 = kern[7], k8 = kern[8];

    const uint32_t sb0 = (uint32_t)__cvta_generic_to_shared(&si[0][0]);
    const uint32_t sb1 = (uint32_t)__cvta_generic_to_shared(&si[1][0]);

    // Per-thread output base: img*336B + g*48B, both 16B-aligned
    const int othread = img * OUT_ELEMS + g * 12;

    // ---- Prefetch first tile into buffer 0 ----
    int tile = blockIdx.x;
    {
        const float4* src = (const float4*)(x + (long long)tile * IMGS * IMG_ELEMS);
#pragma unroll
        for (int it = 0; it < 5; it++) {
            int i = tid + it * THREADS;
            if (i < F4_PER_TILE) {
                int im = i >> 5, w = i & 31;
                cpasync16(sb0 + (uint32_t)(im * PAD_F4 + w) * 16, src + i);
            }
        }
    }
    cp_commit();

    int cur = 0;
    for (; tile < NTILES; tile += GRID) {
        // ---- Prefetch next tile into the other buffer ----
        // (Safe: si[cur^1] reads from the PREVIOUS iteration were fenced by
        //  the post-compute __syncthreads at the bottom of that iteration.)
        const int nt = tile + GRID;
        if (nt < NTILES) {
            const uint32_t sb = cur ? sb0 : sb1;
            const float4* src = (const float4*)(x + (long long)nt * IMGS * IMG_ELEMS);
#pragma unroll
            for (int it = 0; it < 5; it++) {
                int i = tid + it * THREADS;
                if (i < F4_PER_TILE) {
                    int im = i >> 5, w = i & 31;
                    cpasync16(sb + (uint32_t)(im * PAD_F4 + w) * 16, src + i);
                }
            }
        }
        cp_commit();          // commit (possibly empty) group every iteration
        cp_wait1();           // current tile's (older) group is complete
        __syncthreads();      // all threads see current buffer

        // ---- Compute from si[cur]: 2 output rows (12 floats) per thread ----
        float4 o0, o1, o2;
        {
            const float* base = &si[cur][0] + img * PAD_F + 2 * g * IMG_W;

            float a[8], b[8], c[8], d[8];
            loadrow(a, base);
            loadrow(b, base + IMG_W);
            loadrow(c, base + 2 * IMG_W);
            loadrow(d, base + 3 * IMG_W);

#define CONV9(r0, r1, r2, cc) \
    fmaxf(fmaf(r2[(cc)+2], k8, fmaf(r2[(cc)+1], k7, fmaf(r2[(cc)], k6, \
          fmaf(r1[(cc)+2], k5, fmaf(r1[(cc)+1], k4, fmaf(r1[(cc)], k3, \
          fmaf(r0[(cc)+2], k2, fmaf(r0[(cc)+1], k1, r0[(cc)] * k0)))))))), 0.0f)

            o0.x = CONV9(a, b, c, 0);
            o0.y = CONV9(a, b, c, 1);
            o0.z = CONV9(a, b, c, 2);
            o0.w = CONV9(a, b, c, 3);
            o1.x = CONV9(a, b, c, 4);
            o1.y = CONV9(a, b, c, 5);
            o1.z = CONV9(b, c, d, 0);
            o1.w = CONV9(b, c, d, 1);
            o2.x = CONV9(b, c, d, 2);
            o2.y = CONV9(b, c, d, 3);
            o2.z = CONV9(b, c, d, 4);
            o2.w = CONV9(b, c, d, 5);
#undef CONV9
        }

        // ---- Fence: all warps done reading si[cur] before the NEXT
        //      iteration's cp.async overwrites it. ----
        __syncthreads();

        // ---- Direct store: 3 x STG.128 per thread (all 16B-aligned) ----
        {
            float* dst = out + (long long)tile * IMGS * OUT_ELEMS + othread;
            *(float4*)(dst)     = o0;
            *(float4*)(dst + 4) = o1;
            *(float4*)(dst + 8) = o2;
        }
        cur ^= 1;
    }
}

extern "C" void kernel_launch(void* const* d_in, const int* in_sizes, int n_in,
                              void* d_out, int out_size)
{
    const float* x    = (const float*)d_in[0];   // [4096, 64, 128]
    const float* kern = (const float*)d_in[1];   // [3, 3]
    float* out        = (float*)d_out;           // [4096, 64, 84]

    conv3x3_relu_kernel<<<GRID, THREADS>>>(x, kern, out);
}

// round 8
// speedup vs baseline: 1.2393x; 1.2393x over previous
#include <cuda_runtime.h>
#include <cstdint>

// Fixed problem shapes
#define NIMG      262144     // 4096 * 64 images
#define IMG_ELEMS 128        // 16 x 8
#define IMG_W     8
#define OUT_ELEMS 84         // 14 x 6
#define OUT_W     6

#define THREADS   224                      // 7 warps: warp = row-group, lane = image
#define IMGS      32                       // images per tile
#define NTILES    (NIMG / IMGS)            // 8192

// Input smem: 33 float4 (132 floats) per image -> conflict-free LDS.128
#define PAD_F4   33
#define PAD_F    132

#define NSM           148
#define BLOCKS_PER_SM 5
#define GRID          (NSM * BLOCKS_PER_SM)   // 740 persistent blocks

#define F4_PER_TILE (IMGS * IMG_ELEMS / 4)    // 1024
#define OUT_F4_PER_TILE (IMGS * OUT_ELEMS / 4) // 672 = 3 * 224

__device__ __forceinline__ void cpasync16(uint32_t saddr, const void* g) {
    asm volatile("cp.async.cg.shared.global [%0], [%1], 16;\n"
                 :: "r"(saddr), "l"(g));
}
__device__ __forceinline__ void cp_commit() {
    asm volatile("cp.async.commit_group;\n");
}
__device__ __forceinline__ void cp_wait1() {
    asm volatile("cp.async.wait_group 1;\n");
}

__device__ __forceinline__ void loadrow(float* d, const float* p) {
    float4 lo = *(const float4*)p;
    float4 hi = *(const float4*)(p + 4);
    d[0] = lo.x; d[1] = lo.y; d[2] = lo.z; d[3] = lo.w;
    d[4] = hi.x; d[5] = hi.y; d[6] = hi.z; d[7] = hi.w;
}

__global__ __launch_bounds__(THREADS, BLOCKS_PER_SM)
void conv3x3_relu_kernel(const float* __restrict__ x,
                         const float* __restrict__ kern,
                         float* __restrict__ out)
{
    __shared__ float si[2][IMGS * PAD_F];   // 2 x 16896 B
    __shared__ float so[IMGS * OUT_ELEMS];  // 10752 B, unpadded (STS.128 bank-clean)

    const int tid = threadIdx.x;

    // Thread role: image = lane, 2-output-row group = warp (0..6)
    const int g   = tid >> 5;             // warp-uniform row group
    const int img = tid & 31;             // lane -> conflict-free LDS (stride 132)

    const float k0 = kern[0], k1 = kern[1], k2 = kern[2];
    const float k3 = kern[3], k4 = kern[4], k5 = kern[5];
    const float k6 = kern[6], k7 = kern[7], k8 = kern[8];

    const uint32_t sb0 = (uint32_t)__cvta_generic_to_shared(&si[0][0]);
    const uint32_t sb1 = (uint32_t)__cvta_generic_to_shared(&si[1][0]);

    // Staging target: float4 index img*21 + g*3 (16B-aligned by construction)
    float4* const so4 = (float4*)so;
    float4* const odst4 = so4 + img * (OUT_ELEMS / 4) + g * 3;

    // ---- Prefetch first tile into buffer 0 ----
    int tile = blockIdx.x;
    {
        const float4* src = (const float4*)(x + (long long)tile * IMGS * IMG_ELEMS);
#pragma unroll
        for (int it = 0; it < 5; it++) {
            int i = tid + it * THREADS;
            if (i < F4_PER_TILE) {
                int im = i >> 5, w = i & 31;
                cpasync16(sb0 + (uint32_t)(im * PAD_F4 + w) * 16, src + i);
            }
        }
    }
    cp_commit();

    int cur = 0;
    for (; tile < NTILES; tile += GRID) {
        // ---- Prefetch next tile into the other buffer ----
        const int nt = tile + GRID;
        if (nt < NTILES) {
            const uint32_t sb = cur ? sb0 : sb1;
            const float4* src = (const float4*)(x + (long long)nt * IMGS * IMG_ELEMS);
#pragma unroll
            for (int it = 0; it < 5; it++) {
                int i = tid + it * THREADS;
                if (i < F4_PER_TILE) {
                    int im = i >> 5, w = i & 31;
                    cpasync16(sb + (uint32_t)(im * PAD_F4 + w) * 16, src + i);
                }
            }
        }
        cp_commit();          // commit (possibly empty) group every iteration
        cp_wait1();           // current tile's (older) group is complete
        __syncthreads();      // current buffer visible; so[] free for reuse

        // ---- Compute from si[cur]: 2 output rows (12 floats) per thread ----
        {
            const float* base = &si[cur][0] + img * PAD_F + 2 * g * IMG_W;

            float a[8], b[8], c[8], d[8];
            loadrow(a, base);
            loadrow(b, base + IMG_W);
            loadrow(c, base + 2 * IMG_W);
            loadrow(d, base + 3 * IMG_W);

#define CONV9(r0, r1, r2, cc) \
    fmaxf(fmaf(r2[(cc)+2], k8, fmaf(r2[(cc)+1], k7, fmaf(r2[(cc)], k6, \
          fmaf(r1[(cc)+2], k5, fmaf(r1[(cc)+1], k4, fmaf(r1[(cc)], k3, \
          fmaf(r0[(cc)+2], k2, fmaf(r0[(cc)+1], k1, r0[(cc)] * k0)))))))), 0.0f)

            float4 o0, o1, o2;
            o0.x = CONV9(a, b, c, 0);
            o0.y = CONV9(a, b, c, 1);
            o0.z = CONV9(a, b, c, 2);
            o0.w = CONV9(a, b, c, 3);
            o1.x = CONV9(a, b, c, 4);
            o1.y = CONV9(a, b, c, 5);
            o1.z = CONV9(b, c, d, 0);
            o1.w = CONV9(b, c, d, 1);
            o2.x = CONV9(b, c, d, 2);
            o2.y = CONV9(b, c, d, 3);
            o2.z = CONV9(b, c, d, 4);
            o2.w = CONV9(b, c, d, 5);
#undef CONV9

            // 3 x STS.128, bank-clean (start banks 20*img mod 32, distinct
            // within each quarter-warp)
            odst4[0] = o0;
            odst4[1] = o1;
            odst4[2] = o2;
        }

        __syncthreads();   // compute+staging done; si[cur] reads finished

        // ---- Flush: contiguous LDS.128 -> coalesced STG.128 (3 iters) ----
        {
            float4* __restrict__ out4 =
                (float4*)(out + (long long)tile * IMGS * OUT_ELEMS);
#pragma unroll
            for (int it = 0; it < OUT_F4_PER_TILE / THREADS; it++) {
                int i = tid + it * THREADS;      // [0, 672)
                out4[i] = so4[i];
            }
        }
        // so[] reuse and si[cur] overwrite fenced by next iteration's
        // wait_group + __syncthreads.
        cur ^= 1;
    }
}

extern "C" void kernel_launch(void* const* d_in, const int* in_sizes, int n_in,
                              void* d_out, int out_size)
{
    const float* x    = (const float*)d_in[0];   // [4096, 64, 128]
    const float* kern = (const float*)d_in[1];   // [3, 3]
    float* out        = (float*)d_out;           // [4096, 64, 84]

    conv3x3_relu_kernel<<<GRID, THREADS>>>(x, kern, out);
}

// round 9
// speedup vs baseline: 1.2866x; 1.0382x over previous
#include <cuda_runtime.h>
#include <cstdint>

// Fixed problem shapes
#define NIMG      262144     // 4096 * 64 images
#define IMG_ELEMS 128        // 16 x 8
#define IMG_W     8
#define OUT_ELEMS 84         // 14 x 6
#define OUT_W     6

#define THREADS   224                      // 7 warps: warp = row-group, lane = image
#define IMGS      32                       // images per tile
#define NTILES    (NIMG / IMGS)            // 8192

// Input smem: 33 float4 (132 floats) per image -> conflict-free LDS.128
#define PAD_F4   33
#define PAD_F    132

#define NSM           148
#define BLOCKS_PER_SM 5
#define GRID          (NSM * BLOCKS_PER_SM)   // 740 persistent blocks

#define F4_PER_TILE (IMGS * IMG_ELEMS / 4)     // 1024
#define OUT_F4_PER_TILE (IMGS * OUT_ELEMS / 4) // 672 = 3 * 224

// Dynamic work queue (zero-initialized at module load; reset by last block)
__device__ unsigned int g_counter = 0;
__device__ unsigned int g_done    = 0;

__device__ __forceinline__ void cpasync16(uint32_t saddr, const void* g) {
    asm volatile("cp.async.cg.shared.global [%0], [%1], 16;\n"
                 :: "r"(saddr), "l"(g));
}
__device__ __forceinline__ void cp_commit() {
    asm volatile("cp.async.commit_group;\n");
}
__device__ __forceinline__ void cp_wait1() {
    asm volatile("cp.async.wait_group 1;\n");
}

__device__ __forceinline__ void loadrow(float* d, const float* p) {
    float4 lo = *(const float4*)p;
    float4 hi = *(const float4*)(p + 4);
    d[0] = lo.x; d[1] = lo.y; d[2] = lo.z; d[3] = lo.w;
    d[4] = hi.x; d[5] = hi.y; d[6] = hi.z; d[7] = hi.w;
}

__global__ __launch_bounds__(THREADS, BLOCKS_PER_SM)
void conv3x3_relu_kernel(const float* __restrict__ x,
                         const float* __restrict__ kern,
                         float* __restrict__ out)
{
    __shared__ float si[2][IMGS * PAD_F];   // 2 x 16896 B
    __shared__ float so[IMGS * OUT_ELEMS];  // 10752 B, unpadded
    __shared__ unsigned int s_next;

    const int tid = threadIdx.x;

    // Thread role: image = lane, 2-output-row group = warp (0..6)
    const int g   = tid >> 5;             // warp-uniform row group
    const int img = tid & 31;             // lane -> conflict-free LDS (stride 132)

    const float k0 = kern[0], k1 = kern[1], k2 = kern[2];
    const float k3 = kern[3], k4 = kern[4], k5 = kern[5];
    const float k6 = kern[6], k7 = kern[7], k8 = kern[8];

    const uint32_t sb0 = (uint32_t)__cvta_generic_to_shared(&si[0][0]);
    const uint32_t sb1 = (uint32_t)__cvta_generic_to_shared(&si[1][0]);

    float4* const so4 = (float4*)so;
    float4* const odst4 = so4 + img * (OUT_ELEMS / 4) + g * 3;

    // ---- Grab first tile ----
    if (tid == 0) s_next = atomicAdd(&g_counter, 1u);
    __syncthreads();
    unsigned int tile = s_next;

    // ---- Prefetch first tile into buffer 0 ----
    if (tile < NTILES) {
        const float4* src = (const float4*)(x + (long long)tile * IMGS * IMG_ELEMS);
#pragma unroll
        for (int it = 0; it < 5; it++) {
            int i = tid + it * THREADS;
            if (i < F4_PER_TILE) {
                int im = i >> 5, w = i & 31;
                cpasync16(sb0 + (uint32_t)(im * PAD_F4 + w) * 16, src + i);
            }
        }
    }
    cp_commit();

    // ---- Grab second tile id ----
    if (tid == 0) s_next = atomicAdd(&g_counter, 1u);
    __syncthreads();
    unsigned int nt = s_next;

    int cur = 0;
    while (tile < NTILES) {
        // ---- Prefetch next tile into the other buffer ----
        if (nt < NTILES) {
            const uint32_t sb = cur ? sb0 : sb1;
            const float4* src = (const float4*)(x + (long long)nt * IMGS * IMG_ELEMS);
#pragma unroll
            for (int it = 0; it < 5; it++) {
                int i = tid + it * THREADS;
                if (i < F4_PER_TILE) {
                    int im = i >> 5, w = i & 31;
                    cpasync16(sb + (uint32_t)(im * PAD_F4 + w) * 16, src + i);
                }
            }
        }
        cp_commit();          // commit (possibly empty) group every iteration
        cp_wait1();           // current tile's (older) group is complete
        __syncthreads();      // barrier A: buffer visible; so[] reusable

        // ---- Compute from si[cur]: 2 output rows (12 floats) per thread ----
        {
            const float* base = &si[cur][0] + img * PAD_F + 2 * g * IMG_W;

            float a[8], b[8], c[8], d[8];
            loadrow(a, base);
            loadrow(b, base + IMG_W);
            loadrow(c, base + 2 * IMG_W);
            loadrow(d, base + 3 * IMG_W);

#define CONV9(r0, r1, r2, cc) \
    fmaxf(fmaf(r2[(cc)+2], k8, fmaf(r2[(cc)+1], k7, fmaf(r2[(cc)], k6, \
          fmaf(r1[(cc)+2], k5, fmaf(r1[(cc)+1], k4, fmaf(r1[(cc)], k3, \
          fmaf(r0[(cc)+2], k2, fmaf(r0[(cc)+1], k1, r0[(cc)] * k0)))))))), 0.0f)

            float4 o0, o1, o2;
            o0.x = CONV9(a, b, c, 0);
            o0.y = CONV9(a, b, c, 1);
            o0.z = CONV9(a, b, c, 2);
            o0.w = CONV9(a, b, c, 3);
            o1.x = CONV9(a, b, c, 4);
            o1.y = CONV9(a, b, c, 5);
            o1.z = CONV9(b, c, d, 0);
            o1.w = CONV9(b, c, d, 1);
            o2.x = CONV9(b, c, d, 2);
            o2.y = CONV9(b, c, d, 3);
            o2.z = CONV9(b, c, d, 4);
            o2.w = CONV9(b, c, d, 5);
#undef CONV9

            odst4[0] = o0;      // 3 x STS.128, bank-clean
            odst4[1] = o1;
            odst4[2] = o2;
        }

        // Grab the tile after next (visible to all after barrier B)
        if (tid == 0 && nt < NTILES) s_next = atomicAdd(&g_counter, 1u);

        __syncthreads();   // barrier B: staging done; si[cur] reads finished;
                           //            s_next update visible

        const unsigned int nnt = s_next;   // tile for next iteration's prefetch

        // ---- Flush: contiguous LDS.128 -> coalesced STG.128 (3 iters) ----
        {
            float4* __restrict__ out4 =
                (float4*)(out + (long long)tile * IMGS * OUT_ELEMS);
#pragma unroll
            for (int it = 0; it < OUT_F4_PER_TILE / THREADS; it++) {
                int i = tid + it * THREADS;      // [0, 672)
                out4[i] = so4[i];
            }
        }

        tile = nt;
        nt   = nnt;
        cur ^= 1;
    }

    // ---- Last block resets the queue for the next (graph-replayed) launch ----
    __syncthreads();
    if (tid == 0) {
        __threadfence();
        unsigned int d = atomicAdd(&g_done, 1u);
        if (d == GRID - 1) {
            g_counter = 0;
            g_done    = 0;
            __threadfence();
        }
    }
}

extern "C" void kernel_launch(void* const* d_in, const int* in_sizes, int n_in,
                              void* d_out, int out_size)
{
    const float* x    = (const float*)d_in[0];   // [4096, 64, 128]
    const float* kern = (const float*)d_in[1];   // [3, 3]
    float* out        = (float*)d_out;           // [4096, 64, 84]

    conv3x3_relu_kernel<<<GRID, THREADS>>>(x, kern, out);
}

// round 10
// speedup vs baseline: 1.2918x; 1.0040x over previous
#include <cuda_runtime.h>
#include <cstdint>

// Fixed problem shapes
#define NIMG      262144     // 4096 * 64 images
#define IMG_ELEMS 128        // 16 x 8
#define IMG_W     8
#define OUT_ELEMS 84         // 14 x 6
#define OUT_W     6

#define THREADS   224                      // 7 warps: warp = row-group, lane = image
#define IMGS      32                       // images per tile
#define NTILES    (NIMG / IMGS)            // 8192

// Input smem: 33 float4 (132 floats) per image -> conflict-free LDS.128
#define PAD_F4   33
#define PAD_F    132

#define NSM           148
#define BLOCKS_PER_SM 5
#define GRID          (NSM * BLOCKS_PER_SM)   // 740 persistent blocks

#define F4_PER_TILE (IMGS * IMG_ELEMS / 4)     // 1024
#define OUT_F4_PER_TILE (IMGS * OUT_ELEMS / 4) // 672 = 3 * 224

// Dynamic work queue (zero-initialized at module load; reset by last block)
__device__ unsigned int g_counter = 0;
__device__ unsigned int g_done    = 0;

__device__ __forceinline__ void cpasync16(uint32_t saddr, const void* g) {
    asm volatile("cp.async.cg.shared.global [%0], [%1], 16;\n"
                 :: "r"(saddr), "l"(g));
}
__device__ __forceinline__ void cp_commit() {
    asm volatile("cp.async.commit_group;\n");
}
__device__ __forceinline__ void cp_wait1() {
    asm volatile("cp.async.wait_group 1;\n");
}

__device__ __forceinline__ void loadrow(float* d, const float* p) {
    float4 lo = *(const float4*)p;
    float4 hi = *(const float4*)(p + 4);
    d[0] = lo.x; d[1] = lo.y; d[2] = lo.z; d[3] = lo.w;
    d[4] = hi.x; d[5] = hi.y; d[6] = hi.z; d[7] = hi.w;
}

__global__ __launch_bounds__(THREADS, BLOCKS_PER_SM)
void conv3x3_relu_kernel(const float* __restrict__ x,
                         const float* __restrict__ kern,
                         float* __restrict__ out)
{
    __shared__ float si[2][IMGS * PAD_F];   // 2 x 16896 B
    __shared__ float so[IMGS * OUT_ELEMS];  // 10752 B, unpadded
    __shared__ unsigned int s_next;

    const int tid = threadIdx.x;

    // Thread role: image = lane, 2-output-row group = warp (0..6)
    const int g   = tid >> 5;             // warp-uniform row group
    const int img = tid & 31;             // lane -> conflict-free LDS (stride 132)

    const float k0 = kern[0], k1 = kern[1], k2 = kern[2];
    const float k3 = kern[3], k4 = kern[4], k5 = kern[5];
    const float k6 = kern[6], k7 = kern[7], k8 = kern[8];

    const uint32_t sb0 = (uint32_t)__cvta_generic_to_shared(&si[0][0]);
    const uint32_t sb1 = (uint32_t)__cvta_generic_to_shared(&si[1][0]);

    float4* const so4 = (float4*)so;
    float4* const odst4 = so4 + img * (OUT_ELEMS / 4) + g * 3;

    // ---- Grab first tile ----
    if (tid == 0) s_next = atomicAdd(&g_counter, 1u);
    __syncthreads();
    unsigned int tile = s_next;

    // ---- Prefetch first tile into buffer 0 ----
    if (tile < NTILES) {
        const float4* src = (const float4*)(x + (long long)tile * IMGS * IMG_ELEMS);
#pragma unroll
        for (int it = 0; it < 5; it++) {
            int i = tid + it * THREADS;
            if (i < F4_PER_TILE) {
                int im = i >> 5, w = i & 31;
                cpasync16(sb0 + (uint32_t)(im * PAD_F4 + w) * 16, src + i);
            }
        }
    }
    cp_commit();

    // ---- Grab second tile id ----
    if (tid == 0) s_next = atomicAdd(&g_counter, 1u);
    __syncthreads();
    unsigned int nt = s_next;

    int cur = 0;
    while (tile < NTILES) {
        // ---- Prefetch next tile into the other buffer ----
        if (nt < NTILES) {
            const uint32_t sb = cur ? sb0 : sb1;
            const float4* src = (const float4*)(x + (long long)nt * IMGS * IMG_ELEMS);
#pragma unroll
            for (int it = 0; it < 5; it++) {
                int i = tid + it * THREADS;
                if (i < F4_PER_TILE) {
                    int im = i >> 5, w = i & 31;
                    cpasync16(sb + (uint32_t)(im * PAD_F4 + w) * 16, src + i);
                }
            }
        }
        cp_commit();          // commit (possibly empty) group every iteration
        cp_wait1();           // current tile's (older) group is complete
        __syncthreads();      // barrier A: buffer visible; so[] reusable

        // ---- Compute from si[cur]: 2 output rows (12 floats) per thread ----
        {
            const float* base = &si[cur][0] + img * PAD_F + 2 * g * IMG_W;

            float a[8], b[8], c[8], d[8];
            loadrow(a, base);
            loadrow(b, base + IMG_W);
            loadrow(c, base + 2 * IMG_W);
            loadrow(d, base + 3 * IMG_W);

#define CONV9(r0, r1, r2, cc) \
    fmaxf(fmaf(r2[(cc)+2], k8, fmaf(r2[(cc)+1], k7, fmaf(r2[(cc)], k6, \
          fmaf(r1[(cc)+2], k5, fmaf(r1[(cc)+1], k4, fmaf(r1[(cc)], k3, \
          fmaf(r0[(cc)+2], k2, fmaf(r0[(cc)+1], k1, r0[(cc)] * k0)))))))), 0.0f)

            float4 o0, o1, o2;
            o0.x = CONV9(a, b, c, 0);
            o0.y = CONV9(a, b, c, 1);
            o0.z = CONV9(a, b, c, 2);
            o0.w = CONV9(a, b, c, 3);
            o1.x = CONV9(a, b, c, 4);
            o1.y = CONV9(a, b, c, 5);
            o1.z = CONV9(b, c, d, 0);
            o1.w = CONV9(b, c, d, 1);
            o2.x = CONV9(b, c, d, 2);
            o2.y = CONV9(b, c, d, 3);
            o2.z = CONV9(b, c, d, 4);
            o2.w = CONV9(b, c, d, 5);
#undef CONV9

            odst4[0] = o0;      // 3 x STS.128, bank-clean
            odst4[1] = o1;
            odst4[2] = o2;
        }

        // Grab the tile after next (visible to all after barrier B)
        if (tid == 0 && nt < NTILES) s_next = atomicAdd(&g_counter, 1u);

        __syncthreads();   // barrier B: staging done; si[cur] reads finished;
                           //            s_next update visible

        const unsigned int nnt = s_next;   // tile for next iteration's prefetch

        // ---- Flush: contiguous LDS.128 -> streaming STG.128 (evict-first) ----
        {
            float4* __restrict__ out4 =
                (float4*)(out + (long long)tile * IMGS * OUT_ELEMS);
#pragma unroll
            for (int it = 0; it < OUT_F4_PER_TILE / THREADS; it++) {
                int i = tid + it * THREADS;      // [0, 672)
                __stcs(out4 + i, so4[i]);        // st.global.cs: output is
                                                 // write-once, never re-read
            }
        }

        tile = nt;
        nt   = nnt;
        cur ^= 1;
    }

    // ---- Last block resets the queue for the next (graph-replayed) launch ----
    __syncthreads();
    if (tid == 0) {
        __threadfence();
        unsigned int d = atomicAdd(&g_done, 1u);
        if (d == GRID - 1) {
            g_counter = 0;
            g_done    = 0;
            __threadfence();
        }
    }
}

extern "C" void kernel_launch(void* const* d_in, const int* in_sizes, int n_in,
                              void* d_out, int out_size)
{
    const float* x    = (const float*)d_in[0];   // [4096, 64, 128]
    const float* kern = (const float*)d_in[1];   // [3, 3]
    float* out        = (float*)d_out;           // [4096, 64, 84]

    conv3x3_relu_kernel<<<GRID, THREADS>>>(x, kern, out);
}